// round 1
// baseline (speedup 1.0000x reference)
#include <cuda_runtime.h>
#include <math.h>

#define T_SEQ 2048
#define H     768
#define H3    2304
#define NL    10
#define NIN   384
#define NOUT  384

#define SCAN_BLOCKS 96
#define HPB 8   // h elements per block (8 warps, 1 each)

// ---------------- scratch (no allocation allowed) ----------------
__device__ float g_gi[T_SEQ * H3];       // input projections for current layer
__device__ float g_hbuf0[T_SEQ * H];     // ping-pong layer outputs
__device__ float g_hbuf1[T_SEQ * H];
__device__ unsigned int g_ctr;           // scan step barrier counter

__global__ void zero_ctr_kernel() { g_ctr = 0u; }

// ---------------- GEMM: C[M,N] = A[M,K] * B[N,K]^T + bias[N] ----------------
// BM=BN=128, BK=8, 256 threads, 8x8 register tile per thread.
__global__ void __launch_bounds__(256) gemm_nt_bias_kernel(
    const float* __restrict__ A, const float* __restrict__ B,
    const float* __restrict__ bias, float* __restrict__ C,
    int M, int N, int K)
{
    __shared__ float As[8][128];
    __shared__ float Bs[8][132];

    const int tid = threadIdx.x;
    const int bm = blockIdx.y * 128;
    const int bn = blockIdx.x * 128;
    const int tr = tid >> 4;      // 0..15
    const int tc = tid & 15;      // 0..15
    const int m0 = tr * 8;
    const int n0 = tc * 8;

    float acc[8][8];
#pragma unroll
    for (int i = 0; i < 8; i++)
#pragma unroll
        for (int j = 0; j < 8; j++) acc[i][j] = 0.f;

    const int arow = tid >> 1;           // 0..127
    const int akk  = (tid & 1) * 4;      // 0 or 4
    const float* Aptr = A + (size_t)(bm + arow) * K + akk;
    const float* Bptr = B + (size_t)(bn + arow) * K + akk;

    for (int k0 = 0; k0 < K; k0 += 8) {
        float4 av = *(const float4*)(Aptr + k0);
        float4 bv = *(const float4*)(Bptr + k0);
        __syncthreads();  // previous tile fully consumed
        As[akk + 0][arow] = av.x; As[akk + 1][arow] = av.y;
        As[akk + 2][arow] = av.z; As[akk + 3][arow] = av.w;
        Bs[akk + 0][arow] = bv.x; Bs[akk + 1][arow] = bv.y;
        Bs[akk + 2][arow] = bv.z; Bs[akk + 3][arow] = bv.w;
        __syncthreads();
#pragma unroll
        for (int k = 0; k < 8; k++) {
            float4 a0 = *(const float4*)&As[k][m0];
            float4 a1 = *(const float4*)&As[k][m0 + 4];
            float4 b0 = *(const float4*)&Bs[k][n0];
            float4 b1 = *(const float4*)&Bs[k][n0 + 4];
            float ra[8] = {a0.x, a0.y, a0.z, a0.w, a1.x, a1.y, a1.z, a1.w};
            float rb[8] = {b0.x, b0.y, b0.z, b0.w, b1.x, b1.y, b1.z, b1.w};
#pragma unroll
            for (int i = 0; i < 8; i++)
#pragma unroll
                for (int j = 0; j < 8; j++)
                    acc[i][j] = fmaf(ra[i], rb[j], acc[i][j]);
        }
    }

#pragma unroll
    for (int i = 0; i < 8; i++) {
        const int row = bm + m0 + i;
#pragma unroll
        for (int j = 0; j < 8; j++)
            C[(size_t)row * N + bn + n0 + j] = acc[i][j] + bias[bn + n0 + j];
    }
}

// ---------------- GRU recurrent scan (persistent, grid-barrier per step) ----------------
// 96 CTAs x 256 threads. Warp w of block b owns h index j = b*8 + w.
// Each lane holds W_hh[j-rows][24 columns] in registers (72 regs).
// Column mapping: c = k6*128 + lane*4 + i  (i in 0..3), k6 in 0..5.
__global__ void __launch_bounds__(256, 1) gru_scan_kernel(
    const float* __restrict__ gi, const float* __restrict__ w_hh,
    const float* __restrict__ b_hh, float* __restrict__ hout)
{
    __shared__ float hs[H];
    const int tid  = threadIdx.x;
    const int warp = tid >> 5;
    const int lane = tid & 31;
    const int j = blockIdx.x * HPB + warp;

    // preload recurrent weights into registers
    float wr0[24], wr1[24], wr2[24];
#pragma unroll
    for (int k6 = 0; k6 < 6; k6++) {
        const int c = k6 * 128 + lane * 4;
        float4 v0 = *(const float4*)(w_hh + (size_t)(0 * H + j) * H + c);
        float4 v1 = *(const float4*)(w_hh + (size_t)(1 * H + j) * H + c);
        float4 v2 = *(const float4*)(w_hh + (size_t)(2 * H + j) * H + c);
        wr0[k6*4+0] = v0.x; wr0[k6*4+1] = v0.y; wr0[k6*4+2] = v0.z; wr0[k6*4+3] = v0.w;
        wr1[k6*4+0] = v1.x; wr1[k6*4+1] = v1.y; wr1[k6*4+2] = v1.z; wr1[k6*4+3] = v1.w;
        wr2[k6*4+0] = v2.x; wr2[k6*4+1] = v2.y; wr2[k6*4+2] = v2.z; wr2[k6*4+3] = v2.w;
    }
    const float bh0 = b_hh[j];
    const float bh1 = b_hh[H + j];
    const float bh2 = b_hh[2 * H + j];

    for (int t = 0; t < T_SEQ; t++) {
        // prefetch input projections (independent of barrier)
        float gir = 0.f, giz = 0.f, gin = 0.f;
        if (lane == 0) {
            const float* g = gi + (size_t)t * H3;
            gir = g[j];
            giz = g[H + j];
            gin = g[2 * H + j];
        }

        float hv[24];
        float hprev = 0.f;
        if (t == 0) {
#pragma unroll
            for (int k = 0; k < 24; k++) hv[k] = 0.f;
        } else {
            // wait until all blocks finished step t-1
            if (tid == 0) {
                const unsigned target = (unsigned)SCAN_BLOCKS * (unsigned)t;
                unsigned v;
                do {
                    asm volatile("ld.acquire.gpu.global.u32 %0, [%1];"
                                 : "=r"(v) : "l"(&g_ctr));
                } while (v < target);
            }
            __syncthreads();
            // stage h_{t-1} into shared memory
            const float* hp = hout + (size_t)(t - 1) * H;
#pragma unroll
            for (int i = 0; i < 3; i++) hs[tid + i * 256] = hp[tid + i * 256];
            __syncthreads();
#pragma unroll
            for (int k6 = 0; k6 < 6; k6++) {
                float4 v = *(const float4*)(hs + k6 * 128 + lane * 4);
                hv[k6*4+0] = v.x; hv[k6*4+1] = v.y; hv[k6*4+2] = v.z; hv[k6*4+3] = v.w;
            }
            hprev = hs[j];
        }

        // three dot products of length 768, split 24 per lane
        float a0 = 0.f, a1 = 0.f, a2 = 0.f;
#pragma unroll
        for (int k = 0; k < 24; k++) {
            a0 = fmaf(wr0[k], hv[k], a0);
            a1 = fmaf(wr1[k], hv[k], a1);
            a2 = fmaf(wr2[k], hv[k], a2);
        }
#pragma unroll
        for (int off = 16; off > 0; off >>= 1) {
            a0 += __shfl_down_sync(0xffffffffu, a0, off);
            a1 += __shfl_down_sync(0xffffffffu, a1, off);
            a2 += __shfl_down_sync(0xffffffffu, a2, off);
        }

        if (lane == 0) {
            const float ghr = a0 + bh0;
            const float ghz = a1 + bh1;
            const float ghn = a2 + bh2;
            const float r = 1.f / (1.f + __expf(-(gir + ghr)));
            const float z = 1.f / (1.f + __expf(-(giz + ghz)));
            const float n = tanhf(gin + r * ghn);
            hout[(size_t)t * H + j] = (1.f - z) * n + z * hprev;
        }

        // release: make h_t visible, then arrive at barrier
        __threadfence();
        __syncthreads();
        if (tid == 0) atomicAdd(&g_ctr, 1u);
    }
}

// ---------------- launch ----------------
extern "C" void kernel_launch(void* const* d_in, const int* in_sizes, int n_in,
                              void* d_out, int out_size)
{
    const float* x    = (const float*)d_in[0];
    const float* wih0 = (const float*)d_in[1];
    const float* whh0 = (const float*)d_in[2];
    const float* bih0 = (const float*)d_in[3];
    const float* bhh0 = (const float*)d_in[4];
    const float* wih  = (const float*)d_in[5];
    const float* whh  = (const float*)d_in[6];
    const float* bih  = (const float*)d_in[7];
    const float* bhh  = (const float*)d_in[8];
    const float* fcw  = (const float*)d_in[9];
    const float* fcb  = (const float*)d_in[10];

    float *gi, *hb0, *hb1;
    cudaGetSymbolAddress((void**)&gi,  g_gi);
    cudaGetSymbolAddress((void**)&hb0, g_hbuf0);
    cudaGetSymbolAddress((void**)&hb1, g_hbuf1);
    float* hb[2] = {hb0, hb1};

    const float* cur = x;
    for (int l = 0; l < NL; l++) {
        const float* wih_l = (l == 0) ? wih0 : wih + (size_t)(l - 1) * H3 * H;
        const float* whh_l = (l == 0) ? whh0 : whh + (size_t)(l - 1) * H3 * H;
        const float* bih_l = (l == 0) ? bih0 : bih + (size_t)(l - 1) * H3;
        const float* bhh_l = (l == 0) ? bhh0 : bhh + (size_t)(l - 1) * H3;
        const int K = (l == 0) ? NIN : H;

        dim3 grid_gi(H3 / 128, T_SEQ / 128);
        gemm_nt_bias_kernel<<<grid_gi, 256>>>(cur, wih_l, bih_l, gi, T_SEQ, H3, K);

        zero_ctr_kernel<<<1, 1>>>();

        float* ho = hb[l & 1];
        gru_scan_kernel<<<SCAN_BLOCKS, 256>>>(gi, whh_l, bhh_l, ho);
        cur = ho;
    }

    dim3 grid_fc(NOUT / 128, T_SEQ / 128);
    gemm_nt_bias_kernel<<<grid_fc, 256>>>(cur, fcw, fcb, (float*)d_out,
                                          T_SEQ, NOUT, H);
}